// round 3
// baseline (speedup 1.0000x reference)
#include <cuda_runtime.h>

#define BB 2
#define NN 2048
#define MM 4096
#define DD 1024
#define HH 16
#define EE 8
#define TK 2
#define HDIM 64
#define CHUNK 512            // MM / EE
#define ATT_SCALE 0.125f     // 1/sqrt(64)

// ------------------------- scratch (device globals; no allocs) ---------------
__device__ float g_Kp[BB * MM * DD];
__device__ float g_Vp[BB * MM * DD];
__device__ float g_Qp[(size_t)BB * NN * TK * DD];
__device__ float g_Ao[(size_t)BB * NN * TK * DD];
__device__ float g_Go[(size_t)BB * NN * TK * DD];
__device__ int   g_idx[BB * NN * TK];
__device__ float g_w[BB * NN * TK];
__device__ int   g_qlist[BB * EE * NN];
__device__ int   g_slist[BB * EE * NN];
__device__ int   g_cnt[BB * EE];

// ------------------------- cp.async helpers ----------------------------------
__device__ __forceinline__ unsigned smem_u32p(const void* p) {
    return (unsigned)__cvta_generic_to_shared(p);
}
__device__ __forceinline__ void cp_async16(unsigned dst, const float* src) {
    asm volatile("cp.async.cg.shared.global [%0], [%1], 16;\n" :: "r"(dst), "l"(src));
}
__device__ __forceinline__ void cp_commit() {
    asm volatile("cp.async.commit_group;\n" ::: "memory");
}
__device__ __forceinline__ void cp_wait_all() {
    asm volatile("cp.async.wait_group 0;\n" ::: "memory");
}

// ------------------------- small kernels -------------------------------------
__global__ void zero_cnt_kernel() {
    if (threadIdx.x < BB * EE) g_cnt[threadIdx.x] = 0;
}

__global__ void router_kernel(const float* __restrict__ q,
                              const float* __restrict__ Wr,
                              const float* __restrict__ br) {
    int lane = threadIdx.x & 31;
    int qid = blockIdx.x * (blockDim.x >> 5) + (threadIdx.x >> 5);
    if (qid >= BB * NN) return;
    const float* qrow = q + (size_t)qid * DD;
    float acc[EE];
#pragma unroll
    for (int e = 0; e < EE; e++) acc[e] = 0.f;
    for (int d = lane; d < DD; d += 32) {
        float qv = qrow[d];
        const float4* w4 = reinterpret_cast<const float4*>(Wr + d * EE);
        float4 w0 = w4[0], w1 = w4[1];
        acc[0] += qv * w0.x; acc[1] += qv * w0.y;
        acc[2] += qv * w0.z; acc[3] += qv * w0.w;
        acc[4] += qv * w1.x; acc[5] += qv * w1.y;
        acc[6] += qv * w1.z; acc[7] += qv * w1.w;
    }
#pragma unroll
    for (int e = 0; e < EE; e++) {
#pragma unroll
        for (int o = 16; o > 0; o >>= 1)
            acc[e] += __shfl_xor_sync(0xffffffffu, acc[e], o);
    }
    if (lane == 0) {
        float v[EE];
#pragma unroll
        for (int e = 0; e < EE; e++) v[e] = acc[e] + br[e];
        int i0 = 0;
#pragma unroll
        for (int e = 1; e < EE; e++) if (v[e] > v[i0]) i0 = e;
        int i1 = (i0 == 0) ? 1 : 0;
#pragma unroll
        for (int e = 0; e < EE; e++) if (e != i0 && v[e] > v[i1]) i1 = e;
        float ex = __expf(v[i1] - v[i0]);
        float inv = 1.f / (1.f + ex);
        g_idx[qid * 2 + 0] = i0;
        g_idx[qid * 2 + 1] = i1;
        g_w[qid * 2 + 0] = inv;
        g_w[qid * 2 + 1] = ex * inv;
    }
}

__global__ void compact_kernel() {
    int t = blockIdx.x * blockDim.x + threadIdx.x;
    if (t >= BB * NN * TK) return;
    int qid = t >> 1, s = t & 1;
    int b = qid / NN, n = qid % NN;
    int e = g_idx[t];
    int pos = atomicAdd(&g_cnt[b * EE + e], 1);
    g_qlist[(b * EE + e) * NN + pos] = n;
    g_slist[(b * EE + e) * NN + pos] = s;
}

// ------------------- pipelined 128x128x16 fp32 GEMM core ----------------------
// 256 threads, 8x8 micro-tile. Double-buffered smem; B via cp.async, A via
// register staging + transposed STS. One barrier per K-tile.
#define KT 16
#define NKT (DD / KT)

__device__ __forceinline__ void gemm_core_pipe(const float* rowA,  // null => zero rows
                                               const float* Bsrc0,
                                               const float* Bsrc1,
                                               float (&acc)[8][8]) {
    __shared__ float As[2][KT][128];
    __shared__ float Bs[2][KT][128];
    int tid = threadIdx.x;
    int tx = tid & 15, ty = tid >> 4;
    int mA = tid >> 1, kA = (tid & 1) * 8;
    unsigned b0d0 = smem_u32p(&Bs[0][(tid) >> 5][((tid) & 31) * 4]);
    unsigned b0d1 = smem_u32p(&Bs[0][(tid + 256) >> 5][((tid + 256) & 31) * 4]);
    unsigned b1d0 = smem_u32p(&Bs[1][(tid) >> 5][((tid) & 31) * 4]);
    unsigned b1d1 = smem_u32p(&Bs[1][(tid + 256) >> 5][((tid + 256) & 31) * 4]);

    float a[8];
#pragma unroll
    for (int j = 0; j < 8; j++) a[j] = 0.f;
    if (rowA) {
        float4 t0 = *reinterpret_cast<const float4*>(rowA);
        float4 t1 = *reinterpret_cast<const float4*>(rowA + 4);
        a[0] = t0.x; a[1] = t0.y; a[2] = t0.z; a[3] = t0.w;
        a[4] = t1.x; a[5] = t1.y; a[6] = t1.z; a[7] = t1.w;
    }
#pragma unroll
    for (int j = 0; j < 8; j++) As[0][kA + j][mA] = a[j];
    cp_async16(b0d0, Bsrc0);
    cp_async16(b0d1, Bsrc1);
    cp_commit();

    for (int kt = 0; kt < NKT; kt++) {
        int cur = kt & 1;
        cp_wait_all();
        __syncthreads();
        if (kt + 1 < NKT) {
            cp_async16(cur ? b0d0 : b1d0, Bsrc0 + (size_t)(kt + 1) * KT * DD);
            cp_async16(cur ? b0d1 : b1d1, Bsrc1 + (size_t)(kt + 1) * KT * DD);
            cp_commit();
            if (rowA) {
                float4 t0 = *reinterpret_cast<const float4*>(rowA + (kt + 1) * KT);
                float4 t1 = *reinterpret_cast<const float4*>(rowA + (kt + 1) * KT + 4);
                a[0] = t0.x; a[1] = t0.y; a[2] = t0.z; a[3] = t0.w;
                a[4] = t1.x; a[5] = t1.y; a[6] = t1.z; a[7] = t1.w;
            }
        }
#pragma unroll
        for (int k = 0; k < KT; k++) {
            float av[8], bv[8];
            *reinterpret_cast<float4*>(av)     = *reinterpret_cast<const float4*>(&As[cur][k][ty * 8]);
            *reinterpret_cast<float4*>(av + 4) = *reinterpret_cast<const float4*>(&As[cur][k][ty * 8 + 4]);
            *reinterpret_cast<float4*>(bv)     = *reinterpret_cast<const float4*>(&Bs[cur][k][tx * 8]);
            *reinterpret_cast<float4*>(bv + 4) = *reinterpret_cast<const float4*>(&Bs[cur][k][tx * 8 + 4]);
#pragma unroll
            for (int i = 0; i < 8; i++)
#pragma unroll
                for (int j = 0; j < 8; j++)
                    acc[i][j] += av[i] * bv[j];
        }
        if (kt + 1 < NKT) {
#pragma unroll
            for (int j = 0; j < 8; j++) As[cur ^ 1][kA + j][mA] = a[j];
        }
    }
}

// K/V projection
__global__ __launch_bounds__(256, 2) void kvproj_kernel(
    const float* __restrict__ keys, const float* __restrict__ values,
    const float* __restrict__ Wk, const float* __restrict__ Wv,
    const float* __restrict__ bk, const float* __restrict__ bv) {
    int z = blockIdx.z;
    int which = z & 1, be = z >> 1;
    int b = be / EE, e = be % EE;
    const float* A    = (which ? values : keys) + ((size_t)b * MM + e * CHUNK) * DD;
    const float* W    = (which ? Wv : Wk) + (size_t)e * DD * DD;
    const float* bias = (which ? bv : bk) + e * DD;
    float* C          = (which ? g_Vp : g_Kp) + ((size_t)b * MM + e * CHUNK) * DD;

    int m0 = blockIdx.y * 128, n0 = blockIdx.x * 128;
    int tid = threadIdx.x, tx = tid & 15, ty = tid >> 4;
    const float* rowA = A + (size_t)(m0 + (tid >> 1)) * DD + (tid & 1) * 8;
    const float* Bsrc0 = W + (size_t)(tid >> 5) * DD + n0 + (tid & 31) * 4;
    const float* Bsrc1 = W + (size_t)((tid + 256) >> 5) * DD + n0 + ((tid + 256) & 31) * 4;

    float acc[8][8];
#pragma unroll
    for (int i = 0; i < 8; i++)
#pragma unroll
        for (int j = 0; j < 8; j++) acc[i][j] = 0.f;

    gemm_core_pipe(rowA, Bsrc0, Bsrc1, acc);

    float bvals[8];
#pragma unroll
    for (int j = 0; j < 8; j++) bvals[j] = bias[n0 + tx * 8 + j];
#pragma unroll
    for (int i = 0; i < 8; i++) {
        float* crow = C + (size_t)(m0 + ty * 8 + i) * DD + n0 + tx * 8;
        float4 o0 = make_float4(acc[i][0] + bvals[0], acc[i][1] + bvals[1],
                                acc[i][2] + bvals[2], acc[i][3] + bvals[3]);
        float4 o1 = make_float4(acc[i][4] + bvals[4], acc[i][5] + bvals[5],
                                acc[i][6] + bvals[6], acc[i][7] + bvals[7]);
        *reinterpret_cast<float4*>(crow)     = o0;
        *reinterpret_cast<float4*>(crow + 4) = o1;
    }
}

// Grouped (gathered) GEMM. PHASE 0: queries -> g_Qp. PHASE 1: g_Ao -> g_Go.
template <int PHASE>
__global__ __launch_bounds__(256, 2) void grouped_gemm_kernel(
    const float* __restrict__ Aglobal,
    const float* __restrict__ Wall,
    const float* __restrict__ ball) {
    int be = blockIdx.z;
    int cnt = g_cnt[be];
    int m0 = blockIdx.y * 128;
    if (m0 >= cnt) return;
    int b = be / EE, e = be % EE;
    int n0 = blockIdx.x * 128;
    int tid = threadIdx.x, tx = tid & 15, ty = tid >> 4;

    const float* W = Wall + (size_t)e * DD * DD;
    const float* bias = ball + e * DD;

    const float* rowA = nullptr;
    {
        int mg = m0 + (tid >> 1);
        if (mg < cnt) {
            int n = g_qlist[be * NN + mg];
            int s = g_slist[be * NN + mg];
            if (PHASE == 0) {
                rowA = Aglobal + ((size_t)b * NN + n) * DD + (tid & 1) * 8;
                (void)s;
            } else {
                rowA = g_Ao + (((size_t)b * NN + n) * TK + s) * DD + (tid & 1) * 8;
            }
        }
    }
    const float* Bsrc0 = W + (size_t)(tid >> 5) * DD + n0 + (tid & 31) * 4;
    const float* Bsrc1 = W + (size_t)((tid + 256) >> 5) * DD + n0 + ((tid + 256) & 31) * 4;

    float acc[8][8];
#pragma unroll
    for (int i = 0; i < 8; i++)
#pragma unroll
        for (int j = 0; j < 8; j++) acc[i][j] = 0.f;

    gemm_core_pipe(rowA, Bsrc0, Bsrc1, acc);

    float* Cdst = (PHASE == 0) ? g_Qp : g_Go;
    float bvals[8];
#pragma unroll
    for (int j = 0; j < 8; j++) bvals[j] = bias[n0 + tx * 8 + j];
#pragma unroll
    for (int i = 0; i < 8; i++) {
        int mg = m0 + ty * 8 + i;
        if (mg < cnt) {
            int n = g_qlist[be * NN + mg];
            int s = g_slist[be * NN + mg];
            float* crow = Cdst + (((size_t)b * NN + n) * TK + s) * DD + n0 + tx * 8;
            float4 o0 = make_float4(acc[i][0] + bvals[0], acc[i][1] + bvals[1],
                                    acc[i][2] + bvals[2], acc[i][3] + bvals[3]);
            float4 o1 = make_float4(acc[i][4] + bvals[4], acc[i][5] + bvals[5],
                                    acc[i][6] + bvals[6], acc[i][7] + bvals[7]);
            *reinterpret_cast<float4*>(crow)     = o0;
            *reinterpret_cast<float4*>(crow + 4) = o1;
        }
    }
}

// ------------------------- fused attention (flash-style, online softmax) -----
// Block = (head, 32-query tile, be). 256 threads = 8 warps; warp owns 4 queries.
// 4 key-tiles of 128; QK micro 4q x 4k, AV micro 4q x 2d; probs via smem tile.
#define AQT  32
#define KTILE 128
#define P_KT 132
#define P_V  68
#define P_P  36
#define ATTN_SMEM_FLOATS (64 * AQT + 64 * P_KT + KTILE * P_V + KTILE * P_P)
#define ATTN_SMEM_BYTES  (ATTN_SMEM_FLOATS * 4)

__global__ __launch_bounds__(256, 2) void attn_kernel() {
    extern __shared__ float sm[];
    float* qT = sm;                    // [64 d][32 q], pre-scaled
    float* kT = qT + 64 * AQT;         // [64 d][128 k + pad]
    float* vS = kT + 64 * P_KT;        // [128 m][64 d + pad]
    float* pS = vS + KTILE * P_V;      // [128 m][32 q + pad]

    int h = blockIdx.x, qt = blockIdx.y, be = blockIdx.z;
    int cnt = g_cnt[be];
    int q0 = qt * AQT;
    if (q0 >= cnt) return;
    int nq = min(AQT, cnt - q0);
    int b = be / EE, e = be % EE;
    int tid = threadIdx.x;
    int lane = tid & 31, warp = tid >> 5;

    // load + scale Q tile (transposed [d][q])
    {
        int qi = tid & 31;
        int d0 = (tid >> 5) * 8;
        float4 v0 = make_float4(0.f, 0.f, 0.f, 0.f), v1 = v0;
        if (qi < nq) {
            int n = g_qlist[be * NN + q0 + qi];
            int s = g_slist[be * NN + q0 + qi];
            const float* qp = g_Qp + (((size_t)b * NN + n) * TK + s) * DD + h * HDIM + d0;
            v0 = *reinterpret_cast<const float4*>(qp);
            v1 = *reinterpret_cast<const float4*>(qp + 4);
        }
        qT[(d0 + 0) * AQT + qi] = v0.x * ATT_SCALE;
        qT[(d0 + 1) * AQT + qi] = v0.y * ATT_SCALE;
        qT[(d0 + 2) * AQT + qi] = v0.z * ATT_SCALE;
        qT[(d0 + 3) * AQT + qi] = v0.w * ATT_SCALE;
        qT[(d0 + 4) * AQT + qi] = v1.x * ATT_SCALE;
        qT[(d0 + 5) * AQT + qi] = v1.y * ATT_SCALE;
        qT[(d0 + 6) * AQT + qi] = v1.z * ATT_SCALE;
        qT[(d0 + 7) * AQT + qi] = v1.w * ATT_SCALE;
    }

    const float* Kb = g_Kp + ((size_t)b * MM + e * CHUNK) * DD + h * HDIM;
    const float* Vb = g_Vp + ((size_t)b * MM + e * CHUNK) * DD + h * HDIM;

    float run_mx[4], run_sum[4], o[4][2];
#pragma unroll
    for (int j = 0; j < 4; j++) {
        run_mx[j] = -1e30f; run_sum[j] = 0.f;
        o[j][0] = 0.f; o[j][1] = 0.f;
    }

    int rowL = tid >> 1;
    int dL = (tid & 1) * 32;

    for (int ktile = 0; ktile < CHUNK / KTILE; ktile++) {
        __syncthreads();   // prior AV reads of vS/pS done; qT ready (1st iter)
        // K tile: transpose into kT[d][m]
        const float* krow = Kb + (size_t)(ktile * KTILE + rowL) * DD + dL;
        const float* vrow = Vb + (size_t)(ktile * KTILE + rowL) * DD + dL;
#pragma unroll
        for (int u = 0; u < 8; u++) {
            float4 kv = *reinterpret_cast<const float4*>(krow + u * 4);
            kT[(dL + u * 4 + 0) * P_KT + rowL] = kv.x;
            kT[(dL + u * 4 + 1) * P_KT + rowL] = kv.y;
            kT[(dL + u * 4 + 2) * P_KT + rowL] = kv.z;
            kT[(dL + u * 4 + 3) * P_KT + rowL] = kv.w;
            *reinterpret_cast<float4*>(&vS[rowL * P_V + dL + u * 4]) =
                *reinterpret_cast<const float4*>(vrow + u * 4);
        }
        __syncthreads();

        // QK: 4 queries (warp) x 4 keys (lane)
        float s4[4][4];
#pragma unroll
        for (int j = 0; j < 4; j++)
#pragma unroll
            for (int i = 0; i < 4; i++) s4[j][i] = 0.f;
#pragma unroll 4
        for (int d = 0; d < HDIM; d++) {
            float4 qv = *reinterpret_cast<const float4*>(&qT[d * AQT + warp * 4]);
            float4 kv = *reinterpret_cast<const float4*>(&kT[d * P_KT + lane * 4]);
            s4[0][0] += qv.x * kv.x; s4[0][1] += qv.x * kv.y; s4[0][2] += qv.x * kv.z; s4[0][3] += qv.x * kv.w;
            s4[1][0] += qv.y * kv.x; s4[1][1] += qv.y * kv.y; s4[1][2] += qv.y * kv.z; s4[1][3] += qv.y * kv.w;
            s4[2][0] += qv.z * kv.x; s4[2][1] += qv.z * kv.y; s4[2][2] += qv.z * kv.z; s4[2][3] += qv.z * kv.w;
            s4[3][0] += qv.w * kv.x; s4[3][1] += qv.w * kv.y; s4[3][2] += qv.w * kv.z; s4[3][3] += qv.w * kv.w;
        }

        // online softmax (warp-local per query)
#pragma unroll
        for (int j = 0; j < 4; j++) {
            float mx = fmaxf(fmaxf(s4[j][0], s4[j][1]), fmaxf(s4[j][2], s4[j][3]));
#pragma unroll
            for (int off = 16; off > 0; off >>= 1)
                mx = fmaxf(mx, __shfl_xor_sync(0xffffffffu, mx, off));
            float nm = fmaxf(run_mx[j], mx);
            float fac = __expf(run_mx[j] - nm);
            run_mx[j] = nm;
            float p0 = __expf(s4[j][0] - nm);
            float p1 = __expf(s4[j][1] - nm);
            float p2 = __expf(s4[j][2] - nm);
            float p3 = __expf(s4[j][3] - nm);
            s4[j][0] = p0; s4[j][1] = p1; s4[j][2] = p2; s4[j][3] = p3;
            float ts = (p0 + p1) + (p2 + p3);
#pragma unroll
            for (int off = 16; off > 0; off >>= 1)
                ts += __shfl_xor_sync(0xffffffffu, ts, off);
            run_sum[j] = run_sum[j] * fac + ts;
            o[j][0] *= fac; o[j][1] *= fac;
        }

        // stage probs: pS[m][q]
#pragma unroll
        for (int i = 0; i < 4; i++) {
            float4 pv = make_float4(s4[0][i], s4[1][i], s4[2][i], s4[3][i]);
            *reinterpret_cast<float4*>(&pS[(lane * 4 + i) * P_P + warp * 4]) = pv;
        }
        __syncthreads();

        // AV: 4 queries (warp) x 2 dims (lane)
#pragma unroll 4
        for (int m = 0; m < KTILE; m++) {
            float4 p4 = *reinterpret_cast<const float4*>(&pS[m * P_P + warp * 4]);
            float2 v2 = *reinterpret_cast<const float2*>(&vS[m * P_V + lane * 2]);
            o[0][0] += p4.x * v2.x; o[0][1] += p4.x * v2.y;
            o[1][0] += p4.y * v2.x; o[1][1] += p4.y * v2.y;
            o[2][0] += p4.z * v2.x; o[2][1] += p4.z * v2.y;
            o[3][0] += p4.w * v2.x; o[3][1] += p4.w * v2.y;
        }
    }

#pragma unroll
    for (int j = 0; j < 4; j++) {
        int qi = warp * 4 + j;
        if (qi < nq) {
            float inv = 1.f / run_sum[j];
            int n = g_qlist[be * NN + q0 + qi];
            int s = g_slist[be * NN + q0 + qi];
            float2 ov = make_float2(o[j][0] * inv, o[j][1] * inv);
            *reinterpret_cast<float2*>(
                g_Ao + (((size_t)b * NN + n) * TK + s) * DD + h * HDIM + lane * 2) = ov;
        }
    }
}

// ------------------------- final combine -------------------------------------
__global__ void combine_kernel(float* __restrict__ out) {
    int t = blockIdx.x * blockDim.x + threadIdx.x;
    int qid = t >> 8;
    int d4 = (t & 255) * 4;
    float w0 = g_w[qid * 2 + 0];
    float w1 = g_w[qid * 2 + 1];
    float4 a = *reinterpret_cast<const float4*>(g_Go + ((size_t)qid * TK + 0) * DD + d4);
    float4 c = *reinterpret_cast<const float4*>(g_Go + ((size_t)qid * TK + 1) * DD + d4);
    float4 o;
    o.x = w0 * a.x + w1 * c.x;
    o.y = w0 * a.y + w1 * c.y;
    o.z = w0 * a.z + w1 * c.z;
    o.w = w0 * a.w + w1 * c.w;
    *reinterpret_cast<float4*>(out + (size_t)qid * DD + d4) = o;
}

// ------------------------- launch --------------------------------------------
extern "C" void kernel_launch(void* const* d_in, const int* in_sizes, int n_in,
                              void* d_out, int out_size) {
    const float* queries = (const float*)d_in[0];
    const float* keys    = (const float*)d_in[1];
    const float* values  = (const float*)d_in[2];
    const float* Wq = (const float*)d_in[3];
    const float* bq = (const float*)d_in[4];
    const float* Wk = (const float*)d_in[5];
    const float* bk = (const float*)d_in[6];
    const float* Wv = (const float*)d_in[7];
    const float* bv = (const float*)d_in[8];
    const float* Wo = (const float*)d_in[9];
    const float* bo = (const float*)d_in[10];
    const float* Wr = (const float*)d_in[11];
    const float* br = (const float*)d_in[12];
    float* out = (float*)d_out;
    (void)in_sizes; (void)n_in; (void)out_size;

    cudaFuncSetAttribute(attn_kernel,
                         cudaFuncAttributeMaxDynamicSharedMemorySize,
                         ATTN_SMEM_BYTES);

    zero_cnt_kernel<<<1, 32>>>();
    router_kernel<<<(BB * NN) / 8, 256>>>(queries, Wr, br);
    compact_kernel<<<(BB * NN * TK) / 256, 256>>>();
    kvproj_kernel<<<dim3(8, 4, BB * EE * 2), 256>>>(keys, values, Wk, Wv, bk, bv);
    grouped_gemm_kernel<0><<<dim3(8, 16, BB * EE), 256>>>(queries, Wq, bq);
    attn_kernel<<<dim3(HH, NN / AQT, BB * EE), 256, ATTN_SMEM_BYTES>>>();
    grouped_gemm_kernel<1><<<dim3(8, 16, BB * EE), 256>>>(nullptr, Wo, bo);
    combine_kernel<<<(BB * NN * DD / 4) / 256, 256>>>(out);
}

// round 5
// speedup vs baseline: 1.5741x; 1.5741x over previous
#include <cuda_runtime.h>
#include <cuda_bf16.h>
#include <cstdint>

#define BB 2
#define NN 2048
#define MM 4096
#define DD 1024
#define HH 16
#define EE 8
#define TK 2
#define HDIM 64
#define CHUNK 512
#define ATT_SCALE 0.125f
#define SLOTS (BB * EE * NN)

#define TKK 32
#define ASTR 40                       // bf16 row stride (pad 8) -> conflict-free ldmatrix
#define PLANE_BYTES (128 * ASTR * 2)  // 10240
#define STAGE_BYTES (4 * PLANE_BYTES) // 40960
#define GEMM_SMEM   (2 * STAGE_BYTES) // 81920

// ------------------------- scratch -------------------------------------------
__device__ float g_Kp[BB * MM * DD];
__device__ float g_Vp[BB * MM * DD];
__device__ float g_Qp[(size_t)SLOTS * DD];
__device__ float g_Ao[(size_t)SLOTS * DD];
__device__ float g_Go[(size_t)SLOTS * DD];
__device__ int   g_idx[BB * NN * TK];
__device__ float g_w[BB * NN * TK];
__device__ int   g_slot[BB * NN * TK];
__device__ int   g_qlist[BB * EE * NN];
__device__ int   g_cnt[BB * EE];
__device__ __nv_bfloat16 g_Kin_h[(size_t)BB * MM * DD];
__device__ __nv_bfloat16 g_Kin_l[(size_t)BB * MM * DD];
__device__ __nv_bfloat16 g_Vin_h[(size_t)BB * MM * DD];
__device__ __nv_bfloat16 g_Vin_l[(size_t)BB * MM * DD];
__device__ __nv_bfloat16 g_Qc_h[(size_t)SLOTS * DD];
__device__ __nv_bfloat16 g_Qc_l[(size_t)SLOTS * DD];
__device__ __nv_bfloat16 g_Ac_h[(size_t)SLOTS * DD];
__device__ __nv_bfloat16 g_Ac_l[(size_t)SLOTS * DD];
__device__ __nv_bfloat16 g_Wt_h[4][(size_t)EE * DD * DD];  // [n][k]; 0=q,1=k,2=v,3=o
__device__ __nv_bfloat16 g_Wt_l[4][(size_t)EE * DD * DD];

// ------------------------- PTX helpers ---------------------------------------
__device__ __forceinline__ uint32_t smem_u32p(const void* p) {
    return (uint32_t)__cvta_generic_to_shared(p);
}
__device__ __forceinline__ void cp_async16(uint32_t dst, const void* src) {
    asm volatile("cp.async.cg.shared.global [%0], [%1], 16;\n" :: "r"(dst), "l"(src));
}
__device__ __forceinline__ void cp_commit() {
    asm volatile("cp.async.commit_group;\n" ::: "memory");
}
__device__ __forceinline__ void cp_wait_all() {
    asm volatile("cp.async.wait_group 0;\n" ::: "memory");
}
__device__ __forceinline__ void ldsm4(uint32_t* r, uint32_t addr) {
    asm volatile("ldmatrix.sync.aligned.m8n8.x4.shared.b16 {%0,%1,%2,%3}, [%4];"
                 : "=r"(r[0]), "=r"(r[1]), "=r"(r[2]), "=r"(r[3]) : "r"(addr));
}
__device__ __forceinline__ void mma_bf16(float* d, const uint32_t* a, const uint32_t* b) {
    asm volatile(
        "mma.sync.aligned.m16n8k16.row.col.f32.bf16.bf16.f32 "
        "{%0,%1,%2,%3}, {%4,%5,%6,%7}, {%8,%9}, {%0,%1,%2,%3};"
        : "+f"(d[0]), "+f"(d[1]), "+f"(d[2]), "+f"(d[3])
        : "r"(a[0]), "r"(a[1]), "r"(a[2]), "r"(a[3]), "r"(b[0]), "r"(b[1]));
}

// ------------------------- small kernels -------------------------------------
__global__ void zero_cnt_kernel() {
    if (threadIdx.x < BB * EE) g_cnt[threadIdx.x] = 0;
}

__global__ void router_kernel(const float* __restrict__ q,
                              const float* __restrict__ Wr,
                              const float* __restrict__ br) {
    int lane = threadIdx.x & 31;
    int qid = blockIdx.x * (blockDim.x >> 5) + (threadIdx.x >> 5);
    if (qid >= BB * NN) return;
    const float* qrow = q + (size_t)qid * DD;
    float acc[EE];
#pragma unroll
    for (int e = 0; e < EE; e++) acc[e] = 0.f;
    for (int d = lane; d < DD; d += 32) {
        float qv = qrow[d];
        const float4* w4 = reinterpret_cast<const float4*>(Wr + d * EE);
        float4 w0 = w4[0], w1 = w4[1];
        acc[0] += qv * w0.x; acc[1] += qv * w0.y;
        acc[2] += qv * w0.z; acc[3] += qv * w0.w;
        acc[4] += qv * w1.x; acc[5] += qv * w1.y;
        acc[6] += qv * w1.z; acc[7] += qv * w1.w;
    }
#pragma unroll
    for (int e = 0; e < EE; e++) {
#pragma unroll
        for (int o = 16; o > 0; o >>= 1)
            acc[e] += __shfl_xor_sync(0xffffffffu, acc[e], o);
    }
    if (lane == 0) {
        float v[EE];
#pragma unroll
        for (int e = 0; e < EE; e++) v[e] = acc[e] + br[e];
        int i0 = 0;
#pragma unroll
        for (int e = 1; e < EE; e++) if (v[e] > v[i0]) i0 = e;
        int i1 = (i0 == 0) ? 1 : 0;
#pragma unroll
        for (int e = 0; e < EE; e++) if (e != i0 && v[e] > v[i1]) i1 = e;
        float ex = __expf(v[i1] - v[i0]);
        float inv = 1.f / (1.f + ex);
        g_idx[qid * 2 + 0] = i0;
        g_idx[qid * 2 + 1] = i1;
        g_w[qid * 2 + 0] = inv;
        g_w[qid * 2 + 1] = ex * inv;
    }
}

__global__ void compact_kernel() {
    int t = blockIdx.x * blockDim.x + threadIdx.x;
    if (t >= BB * NN * TK) return;
    int qid = t >> 1;
    int b = qid / NN, n = qid % NN;
    int be = b * EE + g_idx[t];
    int pos = atomicAdd(&g_cnt[be], 1);
    g_qlist[be * NN + pos] = n;
    g_slot[t] = be * NN + pos;
}

// ------------------------- converts ------------------------------------------
__device__ __forceinline__ void split_bf16(float v, __nv_bfloat16& h, __nv_bfloat16& l) {
    h = __float2bfloat16_rn(v);
    l = __float2bfloat16_rn(v - __bfloat162float(h));
}

__global__ void conv_w_kernel(const float* __restrict__ Wq, const float* __restrict__ Wk,
                              const float* __restrict__ Wv, const float* __restrict__ Wo) {
    __shared__ float sm[32][33];
    int w = blockIdx.z >> 3, e = blockIdx.z & 7;
    const float* src = (w == 0 ? Wq : w == 1 ? Wk : w == 2 ? Wv : Wo) + (size_t)e * DD * DD;
    int k0 = blockIdx.x * 32, n0 = blockIdx.y * 32;
    int tid = threadIdx.x, rr = tid >> 5, cc = tid & 31;
#pragma unroll
    for (int i = 0; i < 4; i++)
        sm[rr + 8 * i][cc] = src[(size_t)(k0 + rr + 8 * i) * DD + n0 + cc];
    __syncthreads();
    __nv_bfloat16* dh = g_Wt_h[w] + (size_t)e * DD * DD;
    __nv_bfloat16* dl = g_Wt_l[w] + (size_t)e * DD * DD;
#pragma unroll
    for (int i = 0; i < 4; i++) {
        __nv_bfloat16 h, l;
        split_bf16(sm[cc][rr + 8 * i], h, l);
        size_t o = (size_t)(n0 + rr + 8 * i) * DD + k0 + cc;
        dh[o] = h; dl[o] = l;
    }
}

__global__ void conv_kv_kernel(const float* __restrict__ keys,
                               const float* __restrict__ values) {
    size_t n4 = (size_t)BB * MM * DD / 4;
    size_t t = (size_t)blockIdx.x * blockDim.x + threadIdx.x;
    int which = (t >= n4);
    size_t i4 = which ? (t - n4) : t;
    float4 v = reinterpret_cast<const float4*>(which ? values : keys)[i4];
    __nv_bfloat16 h[4], l[4];
    split_bf16(v.x, h[0], l[0]); split_bf16(v.y, h[1], l[1]);
    split_bf16(v.z, h[2], l[2]); split_bf16(v.w, h[3], l[3]);
    __nv_bfloat16* dh = which ? g_Vin_h : g_Kin_h;
    __nv_bfloat16* dl = which ? g_Vin_l : g_Kin_l;
    reinterpret_cast<uint2*>(dh)[i4] = *reinterpret_cast<uint2*>(h);
    reinterpret_cast<uint2*>(dl)[i4] = *reinterpret_cast<uint2*>(l);
}

template <int FROM_AO>
__global__ void gather_split_kernel(const float* __restrict__ queries) {
    int be = blockIdx.y;
    int p = blockIdx.x * 2 + (threadIdx.x >> 7);
    if (p >= g_cnt[be]) return;
    int l128 = threadIdx.x & 127;
    int slot = be * NN + p;
    const float* src;
    if (FROM_AO) {
        src = g_Ao + (size_t)slot * DD + l128 * 8;
    } else {
        int b = be / EE;
        int n = g_qlist[be * NN + p];
        src = queries + ((size_t)b * NN + n) * DD + l128 * 8;
    }
    float4 v0 = *reinterpret_cast<const float4*>(src);
    float4 v1 = *reinterpret_cast<const float4*>(src + 4);
    __nv_bfloat16 h[8], l[8];
    split_bf16(v0.x, h[0], l[0]); split_bf16(v0.y, h[1], l[1]);
    split_bf16(v0.z, h[2], l[2]); split_bf16(v0.w, h[3], l[3]);
    split_bf16(v1.x, h[4], l[4]); split_bf16(v1.y, h[5], l[5]);
    split_bf16(v1.z, h[6], l[6]); split_bf16(v1.w, h[7], l[7]);
    __nv_bfloat16* dh = (FROM_AO ? g_Ac_h : g_Qc_h) + (size_t)slot * DD + l128 * 8;
    __nv_bfloat16* dl = (FROM_AO ? g_Ac_l : g_Qc_l) + (size_t)slot * DD + l128 * 8;
    *reinterpret_cast<uint4*>(dh) = *reinterpret_cast<const uint4*>(h);
    *reinterpret_cast<uint4*>(dl) = *reinterpret_cast<const uint4*>(l);
}

// ------------------------- HMMA split-bf16 GEMM core -------------------------
// C[128x128] = A[128xK]*B[128xK]^T, K-major both (row.col). 8 warps, warp tile
// 64x32 = 4x4 m16n8k16 atoms. 3-term split. 2-stage cp.async pipeline.
__device__ __forceinline__ void gemm_body(
    const __nv_bfloat16* __restrict__ Ah, const __nv_bfloat16* __restrict__ Al, int rowA0,
    const __nv_bfloat16* __restrict__ Bh, const __nv_bfloat16* __restrict__ Bl, int rowB0,
    float* __restrict__ C, int crow0, int climit, const float* __restrict__ bias, int n0)
{
    extern __shared__ __align__(128) char smx[];
    int tid = threadIdx.x, lane = tid & 31, warp = tid >> 5;
    uint32_t sm0 = smem_u32p(smx);

    // loader geometry: thread covers rows row0 and row0+64, 8-bf16 col chunk
    int row0 = tid >> 2, col0 = (tid & 3) * 8;
    const __nv_bfloat16* gsrc[4];
    gsrc[0] = Ah + (size_t)(rowA0 + row0) * DD + col0;
    gsrc[1] = Al + (size_t)(rowA0 + row0) * DD + col0;
    gsrc[2] = Bh + (size_t)(rowB0 + row0) * DD + col0;
    gsrc[3] = Bl + (size_t)(rowB0 + row0) * DD + col0;
    uint32_t soff0 = (uint32_t)(row0 * ASTR + col0) * 2;
    uint32_t soff1 = soff0 + 64 * ASTR * 2;

    // ldmatrix lane geometry
    int wr = (warp >> 2) * 64, wc = (warp & 3) * 32;
    uint32_t aRow = (uint32_t)(wr + ((lane >> 3) & 1) * 8 + (lane & 7));
    uint32_t aCol = (uint32_t)((lane >> 4) * 8);
    uint32_t bRow = (uint32_t)(wc + (lane >> 4) * 8 + (lane & 7));
    uint32_t bCol = (uint32_t)(((lane >> 3) & 1) * 8);

    float acc[4][4][4];
#pragma unroll
    for (int i = 0; i < 4; i++)
#pragma unroll
        for (int j = 0; j < 4; j++)
#pragma unroll
            for (int r = 0; r < 4; r++) acc[i][j][r] = 0.f;

    // prologue: stage 0
    {
        uint32_t base = sm0;
#pragma unroll
        for (int p = 0; p < 4; p++) {
            cp_async16(base + p * PLANE_BYTES + soff0, gsrc[p]);
            cp_async16(base + p * PLANE_BYTES + soff1, gsrc[p] + (size_t)64 * DD);
        }
        cp_commit();
    }

    for (int kt = 0; kt < DD / TKK; kt++) {
        int st = kt & 1;
        cp_wait_all();
        __syncthreads();
        if (kt + 1 < DD / TKK) {
            uint32_t base = sm0 + (st ^ 1) * STAGE_BYTES;
            int k0 = (kt + 1) * TKK;
#pragma unroll
            for (int p = 0; p < 4; p++) {
                cp_async16(base + p * PLANE_BYTES + soff0, gsrc[p] + k0);
                cp_async16(base + p * PLANE_BYTES + soff1, gsrc[p] + (size_t)64 * DD + k0);
            }
            cp_commit();
        }
        uint32_t base = sm0 + st * STAGE_BYTES;
#pragma unroll
        for (int k16 = 0; k16 < 2; k16++) {
            uint32_t ah[4][4], al[4][4], bh[4][2], bl[4][2];
#pragma unroll
            for (int ma = 0; ma < 4; ma++) {
                uint32_t addr = base + ((aRow + ma * 16) * ASTR + k16 * 16 + aCol) * 2;
                ldsm4(ah[ma], addr);
                ldsm4(al[ma], addr + PLANE_BYTES);
            }
#pragma unroll
            for (int g = 0; g < 2; g++) {
                uint32_t addr = base + 2 * PLANE_BYTES
                              + ((bRow + g * 16) * ASTR + k16 * 16 + bCol) * 2;
                uint32_t t4[4];
                ldsm4(t4, addr);
                bh[2 * g][0] = t4[0]; bh[2 * g][1] = t4[1];
                bh[2 * g + 1][0] = t4[2]; bh[2 * g + 1][1] = t4[3];
                ldsm4(t4, addr + PLANE_BYTES);
                bl[2 * g][0] = t4[0]; bl[2 * g][1] = t4[1];
                bl[2 * g + 1][0] = t4[2]; bl[2 * g + 1][1] = t4[3];
            }
#pragma unroll
            for (int ma = 0; ma < 4; ma++)
#pragma unroll
                for (int na = 0; na < 4; na++) {
                    mma_bf16(acc[ma][na], ah[ma], bh[na]);
                    mma_bf16(acc[ma][na], ah[ma], bl[na]);
                    mma_bf16(acc[ma][na], al[ma], bh[na]);
                }
        }
    }

    // epilogue
    int rql = lane >> 2, cql = (lane & 3) * 2;
#pragma unroll
    for (int na = 0; na < 4; na++) {
        int colg = n0 + wc + na * 8 + cql;
        float b0 = bias[colg], b1 = bias[colg + 1];
#pragma unroll
        for (int ma = 0; ma < 4; ma++) {
#pragma unroll
            for (int h = 0; h < 2; h++) {
                int rowt = wr + ma * 16 + rql + h * 8;
                if (rowt < climit) {
                    float2 v = make_float2(acc[ma][na][h * 2 + 0] + b0,
                                           acc[ma][na][h * 2 + 1] + b1);
                    *reinterpret_cast<float2*>(C + (size_t)(crow0 + rowt) * DD + colg) = v;
                }
            }
        }
    }
}

__global__ __launch_bounds__(256) void kvproj_mma_kernel(
    const float* __restrict__ bk, const float* __restrict__ bv) {
    int z = blockIdx.z;
    int which = z & 1, be = z >> 1;
    int b = be / EE, e = be % EE;
    int rowA0 = b * MM + e * CHUNK + blockIdx.y * 128;
    gemm_body(which ? g_Vin_h : g_Kin_h, which ? g_Vin_l : g_Kin_l, rowA0,
              g_Wt_h[which ? 2 : 1], g_Wt_l[which ? 2 : 1], e * DD + blockIdx.x * 128,
              which ? g_Vp : g_Kp, rowA0, 128,
              (which ? bv : bk) + e * DD, blockIdx.x * 128);
}

__global__ __launch_bounds__(256) void qproj_mma_kernel(const float* __restrict__ bq) {
    int be = blockIdx.z;
    int cnt = g_cnt[be];
    int m0 = blockIdx.y * 128;
    if (m0 >= cnt) return;
    int e = be % EE;
    gemm_body(g_Qc_h, g_Qc_l, be * NN + m0,
              g_Wt_h[0], g_Wt_l[0], e * DD + blockIdx.x * 128,
              g_Qp, be * NN + m0, cnt - m0, bq + e * DD, blockIdx.x * 128);
}

__global__ __launch_bounds__(256) void oproj_mma_kernel(const float* __restrict__ bo) {
    int be = blockIdx.z;
    int cnt = g_cnt[be];
    int m0 = blockIdx.y * 128;
    if (m0 >= cnt) return;
    int e = be % EE;
    gemm_body(g_Ac_h, g_Ac_l, be * NN + m0,
              g_Wt_h[3], g_Wt_l[3], e * DD + blockIdx.x * 128,
              g_Go, be * NN + m0, cnt - m0, bo + e * DD, blockIdx.x * 128);
}

// ------------------------- fused attention (flash-style) ---------------------
#define AQT  32
#define KTILE 128
#define P_KT 132
#define P_V  68
#define P_P  36
#define ATTN_SMEM_FLOATS (64 * AQT + 64 * P_KT + KTILE * P_V + KTILE * P_P)
#define ATTN_SMEM_BYTES  (ATTN_SMEM_FLOATS * 4)

__global__ __launch_bounds__(256, 2) void attn_kernel() {
    extern __shared__ float sm[];
    float* qT = sm;
    float* kT = qT + 64 * AQT;
    float* vS = kT + 64 * P_KT;
    float* pS = vS + KTILE * P_V;

    int h = blockIdx.x, qt = blockIdx.y, be = blockIdx.z;
    int cnt = g_cnt[be];
    int q0 = qt * AQT;
    if (q0 >= cnt) return;
    int nq = min(AQT, cnt - q0);
    int b = be / EE, e = be % EE;
    int tid = threadIdx.x, lane = tid & 31, warp = tid >> 5;

    {
        int qi = tid & 31, d0 = (tid >> 5) * 8;
        float4 v0 = make_float4(0.f, 0.f, 0.f, 0.f), v1 = v0;
        if (qi < nq) {
            const float* qp = g_Qp + (size_t)(be * NN + q0 + qi) * DD + h * HDIM + d0;
            v0 = *reinterpret_cast<const float4*>(qp);
            v1 = *reinterpret_cast<const float4*>(qp + 4);
        }
        qT[(d0 + 0) * AQT + qi] = v0.x * ATT_SCALE;
        qT[(d0 + 1) * AQT + qi] = v0.y * ATT_SCALE;
        qT[(d0 + 2) * AQT + qi] = v0.z * ATT_SCALE;
        qT[(d0 + 3) * AQT + qi] = v0.w * ATT_SCALE;
        qT[(d0 + 4) * AQT + qi] = v1.x * ATT_SCALE;
        qT[(d0 + 5) * AQT + qi] = v1.y * ATT_SCALE;
        qT[(d0 + 6) * AQT + qi] = v1.z * ATT_SCALE;
        qT[(d0 + 7) * AQT + qi] = v1.w * ATT_SCALE;
    }

    const float* Kb = g_Kp + ((size_t)b * MM + e * CHUNK) * DD + h * HDIM;
    const float* Vb = g_Vp + ((size_t)b * MM + e * CHUNK) * DD + h * HDIM;

    float run_mx[4], run_sum[4], o[4][2];
#pragma unroll
    for (int j = 0; j < 4; j++) {
        run_mx[j] = -1e30f; run_sum[j] = 0.f; o[j][0] = 0.f; o[j][1] = 0.f;
    }
    int rowL = tid >> 1, dL = (tid & 1) * 32;

    for (int ktile = 0; ktile < CHUNK / KTILE; ktile++) {
        __syncthreads();
        const float* krow = Kb + (size_t)(ktile * KTILE + rowL) * DD + dL;
        const float* vrow = Vb + (size_t)(ktile * KTILE + rowL) * DD + dL;
#pragma unroll
        for (int u = 0; u < 8; u++) {
            float4 kv = *reinterpret_cast<const float4*>(krow + u * 4);
            kT[(dL + u * 4 + 0) * P_KT + rowL] = kv.x;
            kT[(dL + u * 4 + 1) * P_KT + rowL] = kv.y;
            kT[(dL + u * 4 + 2) * P_KT + rowL] = kv.z;
            kT[(dL + u * 4 + 3) * P_KT + rowL] = kv.w;
            *reinterpret_cast<float4*>(&vS[rowL * P_V + dL + u * 4]) =
                *reinterpret_cast<const float4*>(vrow + u * 4);
        }
        __syncthreads();

        float s4[4][4];
#pragma unroll
        for (int j = 0; j < 4; j++)
#pragma unroll
            for (int i = 0; i < 4; i++) s4[j][i] = 0.f;
#pragma unroll 4
        for (int d = 0; d < HDIM; d++) {
            float4 qv = *reinterpret_cast<const float4*>(&qT[d * AQT + warp * 4]);
            float4 kv = *reinterpret_cast<const float4*>(&kT[d * P_KT + lane * 4]);
            s4[0][0] += qv.x * kv.x; s4[0][1] += qv.x * kv.y; s4[0][2] += qv.x * kv.z; s4[0][3] += qv.x * kv.w;
            s4[1][0] += qv.y * kv.x; s4[1][1] += qv.y * kv.y; s4[1][2] += qv.y * kv.z; s4[1][3] += qv.y * kv.w;
            s4[2][0] += qv.z * kv.x; s4[2][1] += qv.z * kv.y; s4[2][2] += qv.z * kv.z; s4[2][3] += qv.z * kv.w;
            s4[3][0] += qv.w * kv.x; s4[3][1] += qv.w * kv.y; s4[3][2] += qv.w * kv.z; s4[3][3] += qv.w * kv.w;
        }
#pragma unroll
        for (int j = 0; j < 4; j++) {
            float mx = fmaxf(fmaxf(s4[j][0], s4[j][1]), fmaxf(s4[j][2], s4[j][3]));
#pragma unroll
            for (int off = 16; off > 0; off >>= 1)
                mx = fmaxf(mx, __shfl_xor_sync(0xffffffffu, mx, off));
            float nm = fmaxf(run_mx[j], mx);
            float fac = __expf(run_mx[j] - nm);
            run_mx[j] = nm;
            float p0 = __expf(s4[j][0] - nm), p1 = __expf(s4[j][1] - nm);
            float p2 = __expf(s4[j][2] - nm), p3 = __expf(s4[j][3] - nm);
            s4[j][0] = p0; s4[j][1] = p1; s4[j][2] = p2; s4[j][3] = p3;
            float ts = (p0 + p1) + (p2 + p3);
#pragma unroll
            for (int off = 16; off > 0; off >>= 1)
                ts += __shfl_xor_sync(0xffffffffu, ts, off);
            run_sum[j] = run_sum[j] * fac + ts;
            o[j][0] *= fac; o[j][1] *= fac;
        }
#pragma unroll
        for (int i = 0; i < 4; i++) {
            float4 pv = make_float4(s4[0][i], s4[1][i], s4[2][i], s4[3][i]);
            *reinterpret_cast<float4*>(&pS[(lane * 4 + i) * P_P + warp * 4]) = pv;
        }
        __syncthreads();
#pragma unroll 4
        for (int m = 0; m < KTILE; m++) {
            float4 p4 = *reinterpret_cast<const float4*>(&pS[m * P_P + warp * 4]);
            float2 v2 = *reinterpret_cast<const float2*>(&vS[m * P_V + lane * 2]);
            o[0][0] += p4.x * v2.x; o[0][1] += p4.x * v2.y;
            o[1][0] += p4.y * v2.x; o[1][1] += p4.y * v2.y;
            o[2][0] += p4.z * v2.x; o[2][1] += p4.z * v2.y;
            o[3][0] += p4.w * v2.x; o[3][1] += p4.w * v2.y;
        }
    }
#pragma unroll
    for (int j = 0; j < 4; j++) {
        int qi = warp * 4 + j;
        if (qi < nq) {
            float inv = 1.f / run_sum[j];
            float2 ov = make_float2(o[j][0] * inv, o[j][1] * inv);
            *reinterpret_cast<float2*>(
                g_Ao + (size_t)(be * NN + q0 + qi) * DD + h * HDIM + lane * 2) = ov;
        }
    }
}

// ------------------------- final combine -------------------------------------
__global__ void combine_kernel(float* __restrict__ out) {
    int t = blockIdx.x * blockDim.x + threadIdx.x;
    int qid = t >> 8;
    int d4 = (t & 255) * 4;
    float w0 = g_w[qid * 2 + 0], w1 = g_w[qid * 2 + 1];
    int s0 = g_slot[qid * 2 + 0], s1 = g_slot[qid * 2 + 1];
    float4 a = *reinterpret_cast<const float4*>(g_Go + (size_t)s0 * DD + d4);
    float4 c = *reinterpret_cast<const float4*>(g_Go + (size_t)s1 * DD + d4);
    float4 o;
    o.x = w0 * a.x + w1 * c.x;
    o.y = w0 * a.y + w1 * c.y;
    o.z = w0 * a.z + w1 * c.z;
    o.w = w0 * a.w + w1 * c.w;
    *reinterpret_cast<float4*>(out + (size_t)qid * DD + d4) = o;
}

// ------------------------- launch --------------------------------------------
extern "C" void kernel_launch(void* const* d_in, const int* in_sizes, int n_in,
                              void* d_out, int out_size) {
    const float* queries = (const float*)d_in[0];
    const float* keys    = (const float*)d_in[1];
    const float* values  = (const float*)d_in[2];
    const float* Wq = (const float*)d_in[3];
    const float* bq = (const float*)d_in[4];
    const float* Wk = (const float*)d_in[5];
    const float* bk = (const float*)d_in[6];
    const float* Wv = (const float*)d_in[7];
    const float* bv = (const float*)d_in[8];
    const float* Wo = (const float*)d_in[9];
    const float* bo = (const float*)d_in[10];
    const float* Wr = (const float*)d_in[11];
    const float* br = (const float*)d_in[12];
    float* out = (float*)d_out;
    (void)in_sizes; (void)n_in; (void)out_size;

    cudaFuncSetAttribute(kvproj_mma_kernel, cudaFuncAttributeMaxDynamicSharedMemorySize, GEMM_SMEM);
    cudaFuncSetAttribute(qproj_mma_kernel, cudaFuncAttributeMaxDynamicSharedMemorySize, GEMM_SMEM);
    cudaFuncSetAttribute(oproj_mma_kernel, cudaFuncAttributeMaxDynamicSharedMemorySize, GEMM_SMEM);
    cudaFuncSetAttribute(attn_kernel, cudaFuncAttributeMaxDynamicSharedMemorySize, ATTN_SMEM_BYTES);

    zero_cnt_kernel<<<1, 32>>>();
    router_kernel<<<(BB * NN) / 8, 256>>>(queries, Wr, br);
    compact_kernel<<<(BB * NN * TK) / 256, 256>>>();
    conv_w_kernel<<<dim3(32, 32, 32), 256>>>(Wq, Wk, Wv, Wo);
    conv_kv_kernel<<<(2 * BB * MM * DD / 4) / 256, 256>>>(keys, values);
    gather_split_kernel<0><<<dim3(NN / 2, BB * EE), 256>>>(queries);
    kvproj_mma_kernel<<<dim3(8, 4, BB * EE * 2), 256, GEMM_SMEM>>>(bk, bv);
    qproj_mma_kernel<<<dim3(8, 16, BB * EE), 256, GEMM_SMEM>>>(bq);
    attn_kernel<<<dim3(HH, NN / AQT, BB * EE), 256, ATTN_SMEM_BYTES>>>();
    gather_split_kernel<1><<<dim3(NN / 2, BB * EE), 256>>>(nullptr);
    oproj_mma_kernel<<<dim3(8, 16, BB * EE), 256, GEMM_SMEM>>>(bo);
    combine_kernel<<<(BB * NN * DD / 4) / 256, 256>>>(out);
}

// round 6
// speedup vs baseline: 2.5997x; 1.6515x over previous
#include <cuda_runtime.h>
#include <cuda_bf16.h>
#include <cstdint>

#define BB 2
#define NN 2048
#define MM 4096
#define DD 1024
#define HH 16
#define EE 8
#define TK 2
#define HDIM 64
#define CHUNK 512
#define ATT_SCALE 0.125f
#define SLOTS (BB * EE * NN)

#define TKK 32
#define ASTR 40
#define PLANE_BYTES (128 * ASTR * 2)
#define STAGE_BYTES (4 * PLANE_BYTES)
#define GEMM_SMEM   (2 * STAGE_BYTES)

// attention tiles
#define AQ 128
#define QSTR 72
#define VSTR 136
#define ATTN_SMEM ((4 * 128 * QSTR + 2 * 64 * VSTR) * 2)

// ------------------------- scratch -------------------------------------------
__device__ float g_Go[(size_t)SLOTS * DD];
__device__ int   g_idx[BB * NN * TK];
__device__ float g_w[BB * NN * TK];
__device__ int   g_slot[BB * NN * TK];
__device__ int   g_qlist[BB * EE * NN];
__device__ int   g_cnt[BB * EE];
// GEMM A-operand planes
__device__ __nv_bfloat16 g_Kin_h[(size_t)BB * MM * DD];
__device__ __nv_bfloat16 g_Kin_l[(size_t)BB * MM * DD];
__device__ __nv_bfloat16 g_Vin_h[(size_t)BB * MM * DD];
__device__ __nv_bfloat16 g_Vin_l[(size_t)BB * MM * DD];
__device__ __nv_bfloat16 g_Qch[(size_t)SLOTS * DD];
__device__ __nv_bfloat16 g_Qcl[(size_t)SLOTS * DD];
__device__ __nv_bfloat16 g_Ach[(size_t)SLOTS * DD];   // attention out (compacted)
__device__ __nv_bfloat16 g_Acl[(size_t)SLOTS * DD];
// projected planes for attention
__device__ __nv_bfloat16 g_Kbh[(size_t)BB * MM * DD];
__device__ __nv_bfloat16 g_Kbl[(size_t)BB * MM * DD];
__device__ __nv_bfloat16 g_Vth[(size_t)BB * EE * DD * CHUNK];   // [be][d][key]
__device__ __nv_bfloat16 g_Vtl[(size_t)BB * EE * DD * CHUNK];
__device__ __nv_bfloat16 g_Qph[(size_t)SLOTS * DD];   // scaled
__device__ __nv_bfloat16 g_Qpl[(size_t)SLOTS * DD];
// transposed weights [n][k]; 0=q,1=k,2=v,3=o
__device__ __nv_bfloat16 g_Wt_h[4][(size_t)EE * DD * DD];
__device__ __nv_bfloat16 g_Wt_l[4][(size_t)EE * DD * DD];

// ------------------------- PTX helpers ---------------------------------------
__device__ __forceinline__ uint32_t smem_u32p(const void* p) {
    return (uint32_t)__cvta_generic_to_shared(p);
}
__device__ __forceinline__ void cp_async16(uint32_t dst, const void* src) {
    asm volatile("cp.async.cg.shared.global [%0], [%1], 16;\n" :: "r"(dst), "l"(src));
}
__device__ __forceinline__ void cp_commit() {
    asm volatile("cp.async.commit_group;\n" ::: "memory");
}
__device__ __forceinline__ void cp_wait_all() {
    asm volatile("cp.async.wait_group 0;\n" ::: "memory");
}
__device__ __forceinline__ void ldsm4(uint32_t* r, uint32_t addr) {
    asm volatile("ldmatrix.sync.aligned.m8n8.x4.shared.b16 {%0,%1,%2,%3}, [%4];"
                 : "=r"(r[0]), "=r"(r[1]), "=r"(r[2]), "=r"(r[3]) : "r"(addr));
}
__device__ __forceinline__ void mma_bf16(float* d, const uint32_t* a, const uint32_t* b) {
    asm volatile(
        "mma.sync.aligned.m16n8k16.row.col.f32.bf16.bf16.f32 "
        "{%0,%1,%2,%3}, {%4,%5,%6,%7}, {%8,%9}, {%0,%1,%2,%3};"
        : "+f"(d[0]), "+f"(d[1]), "+f"(d[2]), "+f"(d[3])
        : "r"(a[0]), "r"(a[1]), "r"(a[2]), "r"(a[3]), "r"(b[0]), "r"(b[1]));
}
__device__ __forceinline__ void split_bf16(float v, __nv_bfloat16& h, __nv_bfloat16& l) {
    h = __float2bfloat16_rn(v);
    l = __float2bfloat16_rn(v - __bfloat162float(h));
}
__device__ __forceinline__ uint32_t pack_split(float x, float y, uint32_t& lo) {
    __nv_bfloat162 hi2 = __floats2bfloat162_rn(x, y);
    __nv_bfloat162 lo2 = __floats2bfloat162_rn(x - __bfloat162float(hi2.x),
                                               y - __bfloat162float(hi2.y));
    lo = *reinterpret_cast<uint32_t*>(&lo2);
    return *reinterpret_cast<uint32_t*>(&hi2);
}

// ------------------------- small kernels -------------------------------------
__global__ void zero_cnt_kernel() {
    if (threadIdx.x < BB * EE) g_cnt[threadIdx.x] = 0;
}

__global__ void router_kernel(const float* __restrict__ q,
                              const float* __restrict__ Wr,
                              const float* __restrict__ br) {
    int lane = threadIdx.x & 31;
    int qid = blockIdx.x * (blockDim.x >> 5) + (threadIdx.x >> 5);
    if (qid >= BB * NN) return;
    const float* qrow = q + (size_t)qid * DD;
    float acc[EE];
#pragma unroll
    for (int e = 0; e < EE; e++) acc[e] = 0.f;
    for (int d = lane; d < DD; d += 32) {
        float qv = qrow[d];
        const float4* w4 = reinterpret_cast<const float4*>(Wr + d * EE);
        float4 w0 = w4[0], w1 = w4[1];
        acc[0] += qv * w0.x; acc[1] += qv * w0.y;
        acc[2] += qv * w0.z; acc[3] += qv * w0.w;
        acc[4] += qv * w1.x; acc[5] += qv * w1.y;
        acc[6] += qv * w1.z; acc[7] += qv * w1.w;
    }
#pragma unroll
    for (int e = 0; e < EE; e++) {
#pragma unroll
        for (int o = 16; o > 0; o >>= 1)
            acc[e] += __shfl_xor_sync(0xffffffffu, acc[e], o);
    }
    if (lane == 0) {
        float v[EE];
#pragma unroll
        for (int e = 0; e < EE; e++) v[e] = acc[e] + br[e];
        int i0 = 0;
#pragma unroll
        for (int e = 1; e < EE; e++) if (v[e] > v[i0]) i0 = e;
        int i1 = (i0 == 0) ? 1 : 0;
#pragma unroll
        for (int e = 0; e < EE; e++) if (e != i0 && v[e] > v[i1]) i1 = e;
        float ex = __expf(v[i1] - v[i0]);
        float inv = 1.f / (1.f + ex);
        g_idx[qid * 2 + 0] = i0;
        g_idx[qid * 2 + 1] = i1;
        g_w[qid * 2 + 0] = inv;
        g_w[qid * 2 + 1] = ex * inv;
    }
}

__global__ void compact_kernel() {
    int t = blockIdx.x * blockDim.x + threadIdx.x;
    if (t >= BB * NN * TK) return;
    int qid = t >> 1;
    int b = qid / NN, n = qid % NN;
    int be = b * EE + g_idx[t];
    int pos = atomicAdd(&g_cnt[be], 1);
    g_qlist[be * NN + pos] = n;
    g_slot[t] = be * NN + pos;
}

// ------------------------- converts ------------------------------------------
__global__ void conv_w_kernel(const float* __restrict__ Wq, const float* __restrict__ Wk,
                              const float* __restrict__ Wv, const float* __restrict__ Wo) {
    __shared__ float sm[32][33];
    int w = blockIdx.z >> 3, e = blockIdx.z & 7;
    const float* src = (w == 0 ? Wq : w == 1 ? Wk : w == 2 ? Wv : Wo) + (size_t)e * DD * DD;
    int k0 = blockIdx.x * 32, n0 = blockIdx.y * 32;
    int tid = threadIdx.x, rr = tid >> 5, cc = tid & 31;
#pragma unroll
    for (int i = 0; i < 4; i++)
        sm[rr + 8 * i][cc] = src[(size_t)(k0 + rr + 8 * i) * DD + n0 + cc];
    __syncthreads();
    __nv_bfloat16* dh = g_Wt_h[w] + (size_t)e * DD * DD;
    __nv_bfloat16* dl = g_Wt_l[w] + (size_t)e * DD * DD;
#pragma unroll
    for (int i = 0; i < 4; i++) {
        __nv_bfloat16 h, l;
        split_bf16(sm[cc][rr + 8 * i], h, l);
        size_t o = (size_t)(n0 + rr + 8 * i) * DD + k0 + cc;
        dh[o] = h; dl[o] = l;
    }
}

__global__ void conv_kv_kernel(const float* __restrict__ keys,
                               const float* __restrict__ values) {
    size_t n4 = (size_t)BB * MM * DD / 4;
    size_t t = (size_t)blockIdx.x * blockDim.x + threadIdx.x;
    int which = (t >= n4);
    size_t i4 = which ? (t - n4) : t;
    float4 v = reinterpret_cast<const float4*>(which ? values : keys)[i4];
    __nv_bfloat16 h[4], l[4];
    split_bf16(v.x, h[0], l[0]); split_bf16(v.y, h[1], l[1]);
    split_bf16(v.z, h[2], l[2]); split_bf16(v.w, h[3], l[3]);
    __nv_bfloat16* dh = which ? g_Vin_h : g_Kin_h;
    __nv_bfloat16* dl = which ? g_Vin_l : g_Kin_l;
    reinterpret_cast<uint2*>(dh)[i4] = *reinterpret_cast<uint2*>(h);
    reinterpret_cast<uint2*>(dl)[i4] = *reinterpret_cast<uint2*>(l);
}

__global__ void gather_split_kernel(const float* __restrict__ queries) {
    int be = blockIdx.y;
    int p = blockIdx.x * 2 + (threadIdx.x >> 7);
    if (p >= g_cnt[be]) return;
    int l128 = threadIdx.x & 127;
    int slot = be * NN + p;
    int b = be / EE;
    int n = g_qlist[be * NN + p];
    const float* src = queries + ((size_t)b * NN + n) * DD + l128 * 8;
    float4 v0 = *reinterpret_cast<const float4*>(src);
    float4 v1 = *reinterpret_cast<const float4*>(src + 4);
    __nv_bfloat16 h[8], l[8];
    split_bf16(v0.x, h[0], l[0]); split_bf16(v0.y, h[1], l[1]);
    split_bf16(v0.z, h[2], l[2]); split_bf16(v0.w, h[3], l[3]);
    split_bf16(v1.x, h[4], l[4]); split_bf16(v1.y, h[5], l[5]);
    split_bf16(v1.z, h[6], l[6]); split_bf16(v1.w, h[7], l[7]);
    __nv_bfloat16* dh = g_Qch + (size_t)slot * DD + l128 * 8;
    __nv_bfloat16* dl = g_Qcl + (size_t)slot * DD + l128 * 8;
    *reinterpret_cast<uint4*>(dh) = *reinterpret_cast<const uint4*>(h);
    *reinterpret_cast<uint4*>(dl) = *reinterpret_cast<const uint4*>(l);
}

// ------------------------- HMMA split-bf16 GEMM core -------------------------
// MODE 0: fp32 out. 1: bf16 planes [row][DD]. 2: bf16 planes V-transposed.
// 3: bf16 planes [row][DD], scaled by ATT_SCALE.
template <int MODE>
__device__ __forceinline__ void gemm_body(
    const __nv_bfloat16* __restrict__ Ah, const __nv_bfloat16* __restrict__ Al, int rowA0,
    const __nv_bfloat16* __restrict__ Bh, const __nv_bfloat16* __restrict__ Bl, int rowB0,
    int climit, const float* __restrict__ bias, int n0,
    float* __restrict__ C, __nv_bfloat16* __restrict__ Ph, __nv_bfloat16* __restrict__ Pl,
    long crow0, size_t vtb)
{
    extern __shared__ __align__(128) char smx[];
    int tid = threadIdx.x, lane = tid & 31, warp = tid >> 5;
    uint32_t sm0 = smem_u32p(smx);

    int row0 = tid >> 2, col0 = (tid & 3) * 8;
    const __nv_bfloat16* gsrc[4];
    gsrc[0] = Ah + (size_t)(rowA0 + row0) * DD + col0;
    gsrc[1] = Al + (size_t)(rowA0 + row0) * DD + col0;
    gsrc[2] = Bh + (size_t)(rowB0 + row0) * DD + col0;
    gsrc[3] = Bl + (size_t)(rowB0 + row0) * DD + col0;
    uint32_t soff0 = (uint32_t)(row0 * ASTR + col0) * 2;
    uint32_t soff1 = soff0 + 64 * ASTR * 2;

    int wr = (warp >> 2) * 64, wc = (warp & 3) * 32;
    uint32_t aRow = (uint32_t)(wr + ((lane >> 3) & 1) * 8 + (lane & 7));
    uint32_t aCol = (uint32_t)((lane >> 4) * 8);
    uint32_t bRow = (uint32_t)(wc + (lane >> 4) * 8 + (lane & 7));
    uint32_t bCol = (uint32_t)(((lane >> 3) & 1) * 8);

    float acc[4][4][4];
#pragma unroll
    for (int i = 0; i < 4; i++)
#pragma unroll
        for (int j = 0; j < 4; j++)
#pragma unroll
            for (int r = 0; r < 4; r++) acc[i][j][r] = 0.f;

    {
        uint32_t base = sm0;
#pragma unroll
        for (int p = 0; p < 4; p++) {
            cp_async16(base + p * PLANE_BYTES + soff0, gsrc[p]);
            cp_async16(base + p * PLANE_BYTES + soff1, gsrc[p] + (size_t)64 * DD);
        }
        cp_commit();
    }

    for (int kt = 0; kt < DD / TKK; kt++) {
        int st = kt & 1;
        cp_wait_all();
        __syncthreads();
        if (kt + 1 < DD / TKK) {
            uint32_t base = sm0 + (st ^ 1) * STAGE_BYTES;
            int k0 = (kt + 1) * TKK;
#pragma unroll
            for (int p = 0; p < 4; p++) {
                cp_async16(base + p * PLANE_BYTES + soff0, gsrc[p] + k0);
                cp_async16(base + p * PLANE_BYTES + soff1, gsrc[p] + (size_t)64 * DD + k0);
            }
            cp_commit();
        }
        uint32_t base = sm0 + st * STAGE_BYTES;
#pragma unroll
        for (int k16 = 0; k16 < 2; k16++) {
            uint32_t ah[4][4], al[4][4], bh[4][2], bl[4][2];
#pragma unroll
            for (int ma = 0; ma < 4; ma++) {
                uint32_t addr = base + ((aRow + ma * 16) * ASTR + k16 * 16 + aCol) * 2;
                ldsm4(ah[ma], addr);
                ldsm4(al[ma], addr + PLANE_BYTES);
            }
#pragma unroll
            for (int g = 0; g < 2; g++) {
                uint32_t addr = base + 2 * PLANE_BYTES
                              + ((bRow + g * 16) * ASTR + k16 * 16 + bCol) * 2;
                uint32_t t4[4];
                ldsm4(t4, addr);
                bh[2 * g][0] = t4[0]; bh[2 * g][1] = t4[1];
                bh[2 * g + 1][0] = t4[2]; bh[2 * g + 1][1] = t4[3];
                ldsm4(t4, addr + PLANE_BYTES);
                bl[2 * g][0] = t4[0]; bl[2 * g][1] = t4[1];
                bl[2 * g + 1][0] = t4[2]; bl[2 * g + 1][1] = t4[3];
            }
#pragma unroll
            for (int ma = 0; ma < 4; ma++)
#pragma unroll
                for (int na = 0; na < 4; na++) {
                    mma_bf16(acc[ma][na], ah[ma], bh[na]);
                    mma_bf16(acc[ma][na], ah[ma], bl[na]);
                    mma_bf16(acc[ma][na], al[ma], bh[na]);
                }
        }
    }

    int rql = lane >> 2, cql = (lane & 3) * 2;
#pragma unroll
    for (int na = 0; na < 4; na++) {
        int colg = n0 + wc + na * 8 + cql;
        float b0 = bias[colg], b1 = bias[colg + 1];
#pragma unroll
        for (int ma = 0; ma < 4; ma++) {
#pragma unroll
            for (int hh = 0; hh < 2; hh++) {
                int rowt = wr + ma * 16 + rql + hh * 8;
                if (rowt >= climit) continue;
                float v0 = acc[ma][na][hh * 2 + 0] + b0;
                float v1 = acc[ma][na][hh * 2 + 1] + b1;
                if (MODE == 0) {
                    *reinterpret_cast<float2*>(C + (size_t)(crow0 + rowt) * DD + colg) =
                        make_float2(v0, v1);
                } else if (MODE == 1 || MODE == 3) {
                    if (MODE == 3) { v0 *= ATT_SCALE; v1 *= ATT_SCALE; }
                    uint32_t lo;
                    uint32_t hi = pack_split(v0, v1, lo);
                    size_t idx = ((size_t)(crow0 + rowt) * DD + colg) >> 1;
                    reinterpret_cast<uint32_t*>(Ph)[idx] = hi;
                    reinterpret_cast<uint32_t*>(Pl)[idx] = lo;
                } else {  // MODE 2: transposed V
                    __nv_bfloat16 h0, l0, h1, l1;
                    split_bf16(v0, h0, l0);
                    split_bf16(v1, h1, l1);
                    size_t key = (size_t)(crow0 + rowt);
                    Ph[vtb + (size_t)colg * CHUNK + key] = h0;
                    Pl[vtb + (size_t)colg * CHUNK + key] = l0;
                    Ph[vtb + (size_t)(colg + 1) * CHUNK + key] = h1;
                    Pl[vtb + (size_t)(colg + 1) * CHUNK + key] = l1;
                }
            }
        }
    }
}

__global__ __launch_bounds__(256) void kvproj_mma_kernel(
    const float* __restrict__ bk, const float* __restrict__ bv) {
    int z = blockIdx.z;
    int which = z & 1, be = z >> 1;
    int b = be / EE, e = be % EE;
    int rowA0 = b * MM + e * CHUNK + blockIdx.y * 128;
    if (which == 0) {
        gemm_body<1>(g_Kin_h, g_Kin_l, rowA0,
                     g_Wt_h[1], g_Wt_l[1], e * DD + blockIdx.x * 128,
                     128, bk + e * DD, blockIdx.x * 128,
                     nullptr, g_Kbh, g_Kbl, rowA0, 0);
    } else {
        gemm_body<2>(g_Vin_h, g_Vin_l, rowA0,
                     g_Wt_h[2], g_Wt_l[2], e * DD + blockIdx.x * 128,
                     128, bv + e * DD, blockIdx.x * 128,
                     nullptr, g_Vth, g_Vtl, blockIdx.y * 128, (size_t)be * DD * CHUNK);
    }
}

__global__ __launch_bounds__(256) void qproj_mma_kernel(const float* __restrict__ bq) {
    int be = blockIdx.z;
    int cnt = g_cnt[be];
    int m0 = blockIdx.y * 128;
    if (m0 >= cnt) return;
    int e = be % EE;
    gemm_body<3>(g_Qch, g_Qcl, be * NN + m0,
                 g_Wt_h[0], g_Wt_l[0], e * DD + blockIdx.x * 128,
                 cnt - m0, bq + e * DD, blockIdx.x * 128,
                 nullptr, g_Qph, g_Qpl, be * NN + m0, 0);
}

__global__ __launch_bounds__(256) void oproj_mma_kernel(const float* __restrict__ bo) {
    int be = blockIdx.z;
    int cnt = g_cnt[be];
    int m0 = blockIdx.y * 128;
    if (m0 >= cnt) return;
    int e = be % EE;
    gemm_body<0>(g_Ach, g_Acl, be * NN + m0,
                 g_Wt_h[3], g_Wt_l[3], e * DD + blockIdx.x * 128,
                 cnt - m0, bo + e * DD, blockIdx.x * 128,
                 g_Go, nullptr, nullptr, be * NN + m0, 0);
}

// ------------------------- HMMA flash attention -------------------------------
// block = (head, 128-query tile, be). S tile 128x128 per key-tile; warp owns
// 16 full rows. 3-term split on QK and PV. Online softmax on fragments.
__global__ __launch_bounds__(256, 1) void attn_mma_kernel() {
    extern __shared__ __align__(128) char smb[];
    int h = blockIdx.x, qt = blockIdx.y, be = blockIdx.z;
    int cnt = g_cnt[be];
    int q0 = qt * AQ;
    if (q0 >= cnt) return;
    int nq = min(AQ, cnt - q0);
    int b = be / EE, e = be % EE;
    int tid = threadIdx.x, lane = tid & 31, warp = tid >> 5;
    int wr = warp * 16;

    uint32_t sQ = smem_u32p(smb);
    const uint32_t QPL = 128 * QSTR * 2;
    uint32_t sK = sQ + 2 * QPL;
    uint32_t sV = sK + 2 * QPL;
    const uint32_t VPL = 64 * VSTR * 2;

    // Q tile (scaled at projection time)
#pragma unroll
    for (int i = 0; i < 4; i++) {
        int cid = tid + 256 * i;
        int row = cid >> 3, c8 = (cid & 7) * 8;
        int gr = be * NN + q0 + min(row, nq - 1);
        uint32_t d = (uint32_t)(row * QSTR + c8) * 2;
        cp_async16(sQ + d, g_Qph + (size_t)gr * DD + h * HDIM + c8);
        cp_async16(sQ + QPL + d, g_Qpl + (size_t)gr * DD + h * HDIM + c8);
    }
    cp_commit();

    float oacc[8][4];
#pragma unroll
    for (int a = 0; a < 8; a++)
#pragma unroll
        for (int r = 0; r < 4; r++) oacc[a][r] = 0.f;
    float run_mx0 = -1e30f, run_mx1 = -1e30f, run_s0 = 0.f, run_s1 = 0.f;

    size_t kbase = (size_t)(b * MM + e * CHUNK) * DD + h * HDIM;
    size_t vbase = ((size_t)be * DD + h * HDIM) * CHUNK;

    for (int kt = 0; kt < CHUNK / 128; kt++) {
        __syncthreads();
#pragma unroll
        for (int i = 0; i < 4; i++) {
            int cid = tid + 256 * i;
            int krow = cid >> 3, kc = (cid & 7) * 8;
            uint32_t kd = (uint32_t)(krow * QSTR + kc) * 2;
            size_t ks = kbase + (size_t)(kt * 128 + krow) * DD + kc;
            cp_async16(sK + kd, g_Kbh + ks);
            cp_async16(sK + QPL + kd, g_Kbl + ks);
            int vrow = cid >> 4, vc = (cid & 15) * 8;
            uint32_t vd = (uint32_t)(vrow * VSTR + vc) * 2;
            size_t vs = vbase + (size_t)vrow * CHUNK + kt * 128 + vc;
            cp_async16(sV + vd, g_Vth + vs);
            cp_async16(sV + VPL + vd, g_Vtl + vs);
        }
        cp_commit();
        cp_wait_all();
        __syncthreads();

        // ---- S = Q K^T ----
        float sacc[16][4];
#pragma unroll
        for (int a = 0; a < 16; a++)
#pragma unroll
            for (int r = 0; r < 4; r++) sacc[a][r] = 0.f;

#pragma unroll
        for (int k16 = 0; k16 < 4; k16++) {
            uint32_t aH[4], aL[4];
            uint32_t aaddr = sQ + (uint32_t)((wr + ((lane >> 3) & 1) * 8 + (lane & 7)) * QSTR
                                             + k16 * 16 + (lane >> 4) * 8) * 2;
            ldsm4(aH, aaddr);
            ldsm4(aL, aaddr + QPL);
#pragma unroll
            for (int g = 0; g < 8; g++) {
                uint32_t baddr = sK + (uint32_t)((g * 16 + (lane >> 4) * 8 + (lane & 7)) * QSTR
                                                 + k16 * 16 + ((lane >> 3) & 1) * 8) * 2;
                uint32_t tH[4], tL[4];
                ldsm4(tH, baddr);
                ldsm4(tL, baddr + QPL);
                mma_bf16(sacc[2 * g], aH, tH);
                mma_bf16(sacc[2 * g], aH, tL);
                mma_bf16(sacc[2 * g], aL, tH);
                mma_bf16(sacc[2 * g + 1], aH, tH + 2);
                mma_bf16(sacc[2 * g + 1], aH, tL + 2);
                mma_bf16(sacc[2 * g + 1], aL, tH + 2);
            }
        }

        // ---- online softmax ----
        float mx0 = -1e30f, mx1 = -1e30f;
#pragma unroll
        for (int a = 0; a < 16; a++) {
            mx0 = fmaxf(mx0, fmaxf(sacc[a][0], sacc[a][1]));
            mx1 = fmaxf(mx1, fmaxf(sacc[a][2], sacc[a][3]));
        }
        mx0 = fmaxf(mx0, __shfl_xor_sync(0xffffffffu, mx0, 1));
        mx0 = fmaxf(mx0, __shfl_xor_sync(0xffffffffu, mx0, 2));
        mx1 = fmaxf(mx1, __shfl_xor_sync(0xffffffffu, mx1, 1));
        mx1 = fmaxf(mx1, __shfl_xor_sync(0xffffffffu, mx1, 2));
        float nm0 = fmaxf(run_mx0, mx0), nm1 = fmaxf(run_mx1, mx1);
        float f0 = __expf(run_mx0 - nm0), f1 = __expf(run_mx1 - nm1);
        run_mx0 = nm0; run_mx1 = nm1;
        float s0 = 0.f, s1 = 0.f;
#pragma unroll
        for (int a = 0; a < 16; a++) {
            sacc[a][0] = __expf(sacc[a][0] - nm0); s0 += sacc[a][0];
            sacc[a][1] = __expf(sacc[a][1] - nm0); s0 += sacc[a][1];
            sacc[a][2] = __expf(sacc[a][2] - nm1); s1 += sacc[a][2];
            sacc[a][3] = __expf(sacc[a][3] - nm1); s1 += sacc[a][3];
        }
        s0 += __shfl_xor_sync(0xffffffffu, s0, 1);
        s0 += __shfl_xor_sync(0xffffffffu, s0, 2);
        s1 += __shfl_xor_sync(0xffffffffu, s1, 1);
        s1 += __shfl_xor_sync(0xffffffffu, s1, 2);
        run_s0 = run_s0 * f0 + s0;
        run_s1 = run_s1 * f1 + s1;
#pragma unroll
        for (int a = 0; a < 8; a++) {
            oacc[a][0] *= f0; oacc[a][1] *= f0;
            oacc[a][2] *= f1; oacc[a][3] *= f1;
        }

        // ---- O += P V ---- (S accums re-packed as A operands)
#pragma unroll
        for (int j = 0; j < 8; j++) {
            uint32_t pH[4], pL[4];
            pH[0] = pack_split(sacc[2 * j][0], sacc[2 * j][1], pL[0]);
            pH[1] = pack_split(sacc[2 * j][2], sacc[2 * j][3], pL[1]);
            pH[2] = pack_split(sacc[2 * j + 1][0], sacc[2 * j + 1][1], pL[2]);
            pH[3] = pack_split(sacc[2 * j + 1][2], sacc[2 * j + 1][3], pL[3]);
#pragma unroll
            for (int g = 0; g < 4; g++) {
                uint32_t baddr = sV + (uint32_t)((g * 16 + (lane >> 4) * 8 + (lane & 7)) * VSTR
                                                 + j * 16 + ((lane >> 3) & 1) * 8) * 2;
                uint32_t tH[4], tL[4];
                ldsm4(tH, baddr);
                ldsm4(tL, baddr + VPL);
                mma_bf16(oacc[2 * g], pH, tH);
                mma_bf16(oacc[2 * g], pH, tL);
                mma_bf16(oacc[2 * g], pL, tH);
                mma_bf16(oacc[2 * g + 1], pH, tH + 2);
                mma_bf16(oacc[2 * g + 1], pH, tL + 2);
                mma_bf16(oacc[2 * g + 1], pL, tH + 2);
            }
        }
    }

    // ---- write compacted bf16 split output ----
    float inv0 = 1.f / run_s0, inv1 = 1.f / run_s1;
    int r0 = wr + (lane >> 2);
    int cql = (lane & 3) * 2;
#pragma unroll
    for (int a = 0; a < 8; a++) {
        int colg = h * HDIM + a * 8 + cql;
        if (r0 < nq) {
            uint32_t lo;
            uint32_t hi = pack_split(oacc[a][0] * inv0, oacc[a][1] * inv0, lo);
            size_t idx = ((size_t)(be * NN + q0 + r0) * DD + colg) >> 1;
            reinterpret_cast<uint32_t*>(g_Ach)[idx] = hi;
            reinterpret_cast<uint32_t*>(g_Acl)[idx] = lo;
        }
        if (r0 + 8 < nq) {
            uint32_t lo;
            uint32_t hi = pack_split(oacc[a][2] * inv1, oacc[a][3] * inv1, lo);
            size_t idx = ((size_t)(be * NN + q0 + r0 + 8) * DD + colg) >> 1;
            reinterpret_cast<uint32_t*>(g_Ach)[idx] = hi;
            reinterpret_cast<uint32_t*>(g_Acl)[idx] = lo;
        }
    }
}

// ------------------------- final combine -------------------------------------
__global__ void combine_kernel(float* __restrict__ out) {
    int t = blockIdx.x * blockDim.x + threadIdx.x;
    int qid = t >> 8;
    int d4 = (t & 255) * 4;
    float w0 = g_w[qid * 2 + 0], w1 = g_w[qid * 2 + 1];
    int s0 = g_slot[qid * 2 + 0], s1 = g_slot[qid * 2 + 1];
    float4 a = *reinterpret_cast<const float4*>(g_Go + (size_t)s0 * DD + d4);
    float4 c = *reinterpret_cast<const float4*>(g_Go + (size_t)s1 * DD + d4);
    float4 o;
    o.x = w0 * a.x + w1 * c.x;
    o.y = w0 * a.y + w1 * c.y;
    o.z = w0 * a.z + w1 * c.z;
    o.w = w0 * a.w + w1 * c.w;
    *reinterpret_cast<float4*>(out + (size_t)qid * DD + d4) = o;
}

// ------------------------- launch --------------------------------------------
extern "C" void kernel_launch(void* const* d_in, const int* in_sizes, int n_in,
                              void* d_out, int out_size) {
    const float* queries = (const float*)d_in[0];
    const float* keys    = (const float*)d_in[1];
    const float* values  = (const float*)d_in[2];
    const float* Wq = (const float*)d_in[3];
    const float* bq = (const float*)d_in[4];
    const float* Wk = (const float*)d_in[5];
    const float* bk = (const float*)d_in[6];
    const float* Wv = (const float*)d_in[7];
    const float* bv = (const float*)d_in[8];
    const float* Wo = (const float*)d_in[9];
    const float* bo = (const float*)d_in[10];
    const float* Wr = (const float*)d_in[11];
    const float* br = (const float*)d_in[12];
    float* out = (float*)d_out;
    (void)in_sizes; (void)n_in; (void)out_size;

    cudaFuncSetAttribute(kvproj_mma_kernel, cudaFuncAttributeMaxDynamicSharedMemorySize, GEMM_SMEM);
    cudaFuncSetAttribute(qproj_mma_kernel, cudaFuncAttributeMaxDynamicSharedMemorySize, GEMM_SMEM);
    cudaFuncSetAttribute(oproj_mma_kernel, cudaFuncAttributeMaxDynamicSharedMemorySize, GEMM_SMEM);
    cudaFuncSetAttribute(attn_mma_kernel, cudaFuncAttributeMaxDynamicSharedMemorySize, ATTN_SMEM);

    zero_cnt_kernel<<<1, 32>>>();
    router_kernel<<<(BB * NN) / 8, 256>>>(queries, Wr, br);
    compact_kernel<<<(BB * NN * TK) / 256, 256>>>();
    conv_w_kernel<<<dim3(32, 32, 32), 256>>>(Wq, Wk, Wv, Wo);
    conv_kv_kernel<<<(2 * BB * MM * DD / 4) / 256, 256>>>(keys, values);
    gather_split_kernel<<<dim3(NN / 2, BB * EE), 256>>>(queries);
    kvproj_mma_kernel<<<dim3(8, 4, BB * EE * 2), 256, GEMM_SMEM>>>(bk, bv);
    qproj_mma_kernel<<<dim3(8, 16, BB * EE), 256, GEMM_SMEM>>>(bq);
    attn_mma_kernel<<<dim3(HH, NN / AQ, BB * EE), 256, ATTN_SMEM>>>();
    oproj_mma_kernel<<<dim3(8, 16, BB * EE), 256, GEMM_SMEM>>>(bo);
    combine_kernel<<<(BB * NN * DD / 4) / 256, 256>>>(out);
}